// round 3
// baseline (speedup 1.0000x reference)
#include <cuda_runtime.h>

// SmartDerivatives, round 3: shared-staged, cp.async double-buffered.
// Fix vs R2: x rows are only 8B-aligned (row stride 19800 B), so x staging
// uses 8-byte cp.async (float2, 2475 exact); left frames/chunks are 16B-aligned
// and keep 16-byte cp.async.

constexpr int N       = 100;                 // atoms
constexpr int D       = 4950;                // descriptors (triu pairs)
constexpr int S       = 300;                 // outputs per frame
constexpr int E       = D * 6;               // 29700 left entries per frame
constexpr int BATCH   = 1024;
constexpr int THREADS = 320;
constexpr int C       = 550;                 // descriptors per chunk (9 chunks)
constexpr int NCHUNK  = D / C;               // 9
constexpr int CF      = C * 6;               // 3300 floats per chunk buffer

__device__ __forceinline__ unsigned smem_addr(const void* p) {
    return (unsigned)__cvta_generic_to_shared(p);
}
__device__ __forceinline__ void cp_async16(unsigned dst, const void* src) {
    asm volatile("cp.async.cg.shared.global [%0], [%1], 16;" :: "r"(dst), "l"(src));
}
__device__ __forceinline__ void cp_async8(unsigned dst, const void* src) {
    asm volatile("cp.async.ca.shared.global [%0], [%1], 8;" :: "r"(dst), "l"(src));
}

__global__ void __launch_bounds__(THREADS, 4)
smart_derivatives_kernel(const float* __restrict__ x,
                         const float* __restrict__ left,
                         float* __restrict__ out) {
    __shared__ __align__(16) float xs[D];        // 19.8 KB: x[b, :]
    __shared__ __align__(16) float ls[2][CF];    // 2 x 13.2 KB: left chunks

    const int b = blockIdx.x;
    const int t = threadIdx.x;

    const float* __restrict__ lb = left + (size_t)b * E;

    // ---- prologue: async-stage x row (8B ops) + chunk 0 (16B ops) ----
    {
        const float2* __restrict__ xrow =
            reinterpret_cast<const float2*>(x + (size_t)b * D);
        for (int i = t; i < D / 2; i += THREADS)           // 2475 exact
            cp_async8(smem_addr(&xs[i * 2]), xrow + i);
        const float4* __restrict__ l4 = reinterpret_cast<const float4*>(lb);
        for (int i = t; i < CF / 4; i += THREADS)          // 825 exact
            cp_async16(smem_addr(&ls[0][i * 4]), l4 + i);
        asm volatile("cp.async.commit_group;");
    }

    // Thread t owns output (atom a, dim d).
    const int a = t / 3;
    const int d = t - a * 3;
    const bool active = (t < S);

    // Term cursor: p in [0,99). desc(a,p) monotone increasing.
    int   p    = active ? 0 : 99;
    int   desc = (a > 0) ? (a - 1) : 0;   // first term's descriptor
    float acc  = 0.0f;

    for (int c = 0; c < NCHUNK; ++c) {
        // issue next chunk, then wait for current one
        if (c + 1 < NCHUNK) {
            const float4* __restrict__ src =
                reinterpret_cast<const float4*>(lb + (size_t)(c + 1) * CF);
            float* dstbuf = ls[(c + 1) & 1];
            for (int i = t; i < CF / 4; i += THREADS)
                cp_async16(smem_addr(dstbuf + i * 4), src + i);
            asm volatile("cp.async.commit_group;");
            asm volatile("cp.async.wait_group 1;");   // current chunk landed
        } else {
            asm volatile("cp.async.wait_group 0;");
        }
        __syncthreads();

        const float* __restrict__ lc = ls[c & 1];
        const int c0   = c * C;
        const int cend = c0 + C;

        while (p < 99 && desc < cend) {
            const int off = (p < a) ? 3 : 0;     // a is jj -> slots 3..5
            acc = fmaf(lc[(desc - c0) * 6 + off + d], xs[desc], acc);
            const int pn = p + 1;
            // incremental desc advance:
            //   pn <  a : next pair (pn, a)      delta = N-2-p
            //   pn == a : jump to (a, a+1)       delta = N-1-p
            //   pn >  a : contiguous run         delta = 1
            desc += (pn < a) ? (N - 2 - p) : ((pn == a) ? (N - 1 - p) : 1);
            p = pn;
        }
        __syncthreads();   // protect buf[c&1] before chunk c+2 overwrites it
    }

    if (active) out[(size_t)b * S + t] = acc * acc;
}

extern "C" void kernel_launch(void* const* d_in, const int* in_sizes, int n_in,
                              void* d_out, int out_size) {
    const float* x    = (const float*)d_in[0];   // [BATCH, D] fp32
    const float* left = (const float*)d_in[1];   // [BATCH*E] fp32
    (void)in_sizes; (void)n_in; (void)out_size;

    float* out = (float*)d_out;                  // [BATCH, S] fp32
    smart_derivatives_kernel<<<BATCH, THREADS>>>(x, left, out);
}

// round 4
// speedup vs baseline: 1.3829x; 1.3829x over previous
#include <cuda_runtime.h>

// SmartDerivatives R4: coalesced cp.async double-buffered staging + lean
// two-phase consumer. Thread = one atom (3 dim-accumulators).
//  Row phase:    out(a,d) += sum over atom a's own triu row (slots 0..2),
//                contiguous descs -> clean loop, no conditionals.
//  Column phase: uniform loop over rows i; thread a (a>i) takes its single
//                term from row i (slots 3..5), predicated FMA triple.
// Atom<->lane pairing (a, 99-a) balances row lengths across warps/SMSPs.

constexpr int NA    = 100;
constexpr int D     = 4950;            // triu descriptors
constexpr int E     = D * 6;           // 29700 left entries / frame
constexpr int BATCH = 1024;
constexpr int T     = 128;             // threads (100 active atoms)
constexpr int C     = 550;             // descs per chunk
constexpr int NCH   = 9;
constexpr int CF    = C * 6;           // 3300 floats per chunk

__device__ __forceinline__ unsigned smaddr(const void* p) {
    return (unsigned)__cvta_generic_to_shared(p);
}
__device__ __forceinline__ void cp16(unsigned d, const void* s) {
    asm volatile("cp.async.cg.shared.global [%0], [%1], 16;" :: "r"(d), "l"(s));
}
__device__ __forceinline__ void cp8(unsigned d, const void* s) {
    asm volatile("cp.async.ca.shared.global [%0], [%1], 8;" :: "r"(d), "l"(s));
}

__global__ void __launch_bounds__(T, 4)
smart_derivatives_kernel(const float* __restrict__ x,
                         const float* __restrict__ left,
                         float* __restrict__ out) {
    __shared__ __align__(16) float xs[D];        // 19.8 KB
    __shared__ __align__(16) float ls[2][CF];    // 2 x 13.2 KB

    const int b = blockIdx.x;
    const int t = threadIdx.x;
    const float* __restrict__ lb = left + (size_t)b * E;

    // ---- prologue: stage x row (8B ops, rows only 8B-aligned) + chunk 0 ----
    {
        const float2* __restrict__ xr = (const float2*)(x + (size_t)b * D);
        for (int i = t; i < D / 2; i += T) cp8(smaddr(&xs[2 * i]), xr + i);
        const float4* __restrict__ l4 = (const float4*)lb;
        for (int i = t; i < CF / 4; i += T) cp16(smaddr(&ls[0][4 * i]), l4 + i);
        asm volatile("cp.async.commit_group;");
    }

    // Balanced atom mapping: even t -> t/2, odd t -> 99 - t/2.
    const bool act = (t < NA);
    const int  a   = act ? ((t & 1) ? (99 - (t >> 1)) : (t >> 1)) : 127;
    const int  ra   = act ? (99 * a - (a * (a - 1)) / 2) : 0;  // row start
    const int  rend = act ? (ra + 99 - a) : 0;                 // row end
    const int  a6   = a * 6;

    float acc0 = 0.f, acc1 = 0.f, acc2 = 0.f;
    int icur = 0, rcur = 0;   // uniform column-phase row cursor

    for (int c = 0; c < NCH; ++c) {
        if (c + 1 < NCH) {
            const float4* __restrict__ src = (const float4*)(lb + (c + 1) * CF);
            float* db = ls[(c + 1) & 1];
            for (int i = t; i < CF / 4; i += T) cp16(smaddr(db + 4 * i), src + i);
            asm volatile("cp.async.commit_group;");
            asm volatile("cp.async.wait_group 1;");
        } else {
            asm volatile("cp.async.wait_group 0;");
        }
        __syncthreads();

        const float* __restrict__ lc = ls[c & 1];
        const int c0 = c * C, c1 = c0 + C;

        // ---- row-own phase: contiguous slice of my row inside this chunk ----
        {
            const int lo = (ra > c0) ? ra : c0;
            const int hi = (rend < c1) ? rend : c1;
            for (int dd = lo; dd < hi; ++dd) {
                const float* p = lc + (dd - c0) * 6;
                const float xv = xs[dd];
                acc0 = fmaf(p[0], xv, acc0);
                acc1 = fmaf(p[1], xv, acc1);
                acc2 = fmaf(p[2], xv, acc2);
            }
        }

        // ---- column phase: uniform loop over rows intersecting [c0,c1) ----
        {
            int i = icur, ri = rcur;
            while (i < NA - 1 && ri < c1) {
                const int ub  = ri - i - 1;                 // desc(i,a) = ub + a
                const int alo = (i + 1 > c0 - ub) ? (i + 1) : (c0 - ub);
                const int ahi = (100 < c1 - ub) ? 100 : (c1 - ub);
                if (a >= alo && a < ahi) {
                    const int   lofs = (ub - c0) * 6 + 3 + a6;
                    const float xv   = xs[ub + a];
                    acc0 = fmaf(lc[lofs + 0], xv, acc0);
                    acc1 = fmaf(lc[lofs + 1], xv, acc1);
                    acc2 = fmaf(lc[lofs + 2], xv, acc2);
                }
                const int rn = ri + 99 - i;
                if (rn <= c1) { icur = i + 1; rcur = rn; }  // row fully consumed
                ri = rn; ++i;
            }
        }
        __syncthreads();   // protect ls[c&1] before it is overwritten
    }

    if (act) {
        float* o = out + (size_t)b * 300 + a * 3;
        o[0] = acc0 * acc0;
        o[1] = acc1 * acc1;
        o[2] = acc2 * acc2;
    }
}

extern "C" void kernel_launch(void* const* d_in, const int* in_sizes, int n_in,
                              void* d_out, int out_size) {
    const float* x    = (const float*)d_in[0];   // [BATCH, D] fp32
    const float* left = (const float*)d_in[1];   // [BATCH*E] fp32
    (void)in_sizes; (void)n_in; (void)out_size;

    float* out = (float*)d_out;                  // [BATCH, 300] fp32
    smart_derivatives_kernel<<<BATCH, T>>>(x, left, out);
}

// round 6
// speedup vs baseline: 1.8749x; 1.3558x over previous
#include <cuda_runtime.h>

// SmartDerivatives R6: row-parallel, zero-staging, atomic-free.
// Fix vs R5: combine phase now covers all 300 outputs (R5 block had 256
// threads but guarded `t < 300`, leaving 44 outputs poisoned).
// Warp lanes read CONSECUTIVE descriptors of a triu row (coalesced);
// each desc contributes slots 0..2 to atom i (register accum + shfl
// reduction) and slots 3..5 to atom j (warp-private shared bins).
// Mirrored row pairing (base+w, base+19-w) balances warp work exactly.

constexpr int NA    = 100;
constexpr int D     = 4950;          // triu descriptors
constexpr int E     = D * 6;
constexpr int S3    = NA * 3;        // 300 outputs / frame
constexpr int WARPS = 10;
constexpr int T     = WARPS * 32;    // 320 threads

__device__ __forceinline__ void process_row(
    int i, int lane,
    const float* __restrict__ lb, const float* __restrict__ xb,
    float* __restrict__ ca, float* __restrict__ rowout)
{
    const int base = (i * (2 * NA - i - 1)) >> 1;  // row start desc
    const int len  = NA - 1 - i;                   // descs in row

    float r0 = 0.0f, r1 = 0.0f, r2 = 0.0f;

    #pragma unroll 2
    for (int m = lane; m < len; m += 32) {
        const int desc = base + m;
        const float2* lp = reinterpret_cast<const float2*>(lb + desc * 6);
        const float2 l01 = __ldg(lp);
        const float2 l23 = __ldg(lp + 1);
        const float2 l45 = __ldg(lp + 2);
        const float  xv  = __ldg(xb + desc);

        // atom-i side (slots 0..2)
        r0 = fmaf(l01.x, xv, r0);
        r1 = fmaf(l01.y, xv, r1);
        r2 = fmaf(l23.x, xv, r2);

        // atom-j side (slots 3..5): j unique per lane -> conflict-free RMW
        float* cj = ca + (i + 1 + m) * 3;
        cj[0] += l23.y * xv;
        cj[1] += l45.x * xv;
        cj[2] += l45.y * xv;
    }

    #pragma unroll
    for (int off = 16; off; off >>= 1) {
        r0 += __shfl_down_sync(0xffffffffu, r0, off);
        r1 += __shfl_down_sync(0xffffffffu, r1, off);
        r2 += __shfl_down_sync(0xffffffffu, r2, off);
    }
    if (lane == 0) {
        rowout[i * 3 + 0] = r0;
        rowout[i * 3 + 1] = r1;
        rowout[i * 3 + 2] = r2;
    }
}

__global__ void __launch_bounds__(T)
smart_derivatives_kernel(const float* __restrict__ x,
                         const float* __restrict__ left,
                         float* __restrict__ out) {
    __shared__ float colacc[WARPS][S3];  // 12 KB: per-warp j-side bins
    __shared__ float rowout[S3];         // 1.2 KB: i-side row sums

    const int b    = blockIdx.x;
    const int t    = threadIdx.x;
    const int w    = t >> 5;
    const int lane = t & 31;

    // zero accumulators
    for (int i = t; i < WARPS * S3; i += T) (&colacc[0][0])[i] = 0.0f;
    if (t < S3) rowout[t] = 0.0f;
    __syncthreads();

    const float* __restrict__ lb = left + (size_t)b * E;
    const float* __restrict__ xb = x + (size_t)b * D;
    float* __restrict__ ca = colacc[w];

    // Mirrored pairing per 20-row band: rows (base+w) and (base+19-w).
    // Row lengths of a pair sum to a constant -> perfect warp balance.
    for (int base = 0; base < NA - 1; base += 2 * WARPS) {
        const int i1 = base + w;
        const int i2 = base + (2 * WARPS - 1) - w;
        if (i1 < NA - 1) process_row(i1, lane, lb, xb, ca, rowout);
        if (i2 < NA - 1) process_row(i2, lane, lb, xb, ca, rowout);
    }
    __syncthreads();

    // combine: out(a,d) = (rowout + sum_w colacc[w])^2, coalesced store
    if (t < S3) {                       // 320 threads >= 300: single pass
        float s = rowout[t];
        #pragma unroll
        for (int ww = 0; ww < WARPS; ++ww) s += colacc[ww][t];
        out[(size_t)b * S3 + t] = s * s;
    }
}

extern "C" void kernel_launch(void* const* d_in, const int* in_sizes, int n_in,
                              void* d_out, int out_size) {
    const float* x    = (const float*)d_in[0];   // [BATCH, D] fp32
    const float* left = (const float*)d_in[1];   // [BATCH*E] fp32
    (void)in_sizes; (void)n_in; (void)out_size;

    float* out = (float*)d_out;                  // [BATCH, 300] fp32
    smart_derivatives_kernel<<<1024, T>>>(x, left, out);
}